// round 16
// baseline (speedup 1.0000x reference)
#include <cuda_runtime.h>
#include <cstdint>

// ---------------- hash-grid constants (precomputed from reference config) ----
__constant__ float c_scale[16] = {
    15.0f,          21.1106061f,   29.5549331f,   41.2242532f,
    57.3502375f,    79.6349472f,  110.4304720f,  152.9872000f,
    211.7969070f,  293.0667790f,  405.3746690f,  560.5743900f,
    775.0469010f, 1071.4291820f, 1481.0036600f, 2047.0f
};
__constant__ uint32_t c_res1[5] = {17u, 24u, 32u, 44u, 60u};
__constant__ int c_offset[16] = {
    0, 4920, 18744, 51512, 136696, 352696, 876984, 1401272,
    1925560, 2449848, 2974136, 3498424, 4022712, 4547000, 5071288, 5595576
};

#define THREADS 256
#define ROWS 128
#define ACT_SCALE 4096.0f
#define INV_ACT_SCALE (1.0f / 4096.0f)

// W chunk stream: 12 fp8 chunks (L1 c0..3, L2 c0..3, L3 c0..3).
// chunk image: 64 cols, column-major-per-col: col stride 272 B, elem (k,n) at
// (n&63)*272 + k  (e4m3, 1 byte). All chunks 17408 B.
#define CHUNK_B 17408
__device__ char g_wblob[12 * CHUNK_B];

// ------------------------------------------------------- weight baking ------
__device__ __forceinline__ char f2e4m3(float f) {
    uint16_t u;
    asm("cvt.rn.satfinite.e4m3x2.f32 %0, %1, %2;" : "=h"(u) : "f"(0.0f), "f"(f));
    return (char)(u & 0xFF);
}
__global__ void cvtw_kernel(const float* __restrict__ w1,
                            const float* __restrict__ w2,
                            const float* __restrict__ w3,
                            char* __restrict__ blob) {
    int i = blockIdx.x * 256 + threadIdx.x;   // i = k*256 + n, 65536 total
    int k = i >> 8, n = i & 255;
    int nc = n >> 6;
    int off = (n & 63) * 272 + k;
    blob[(4 + nc) * CHUNK_B + off] = f2e4m3(w2[i]);
    blob[(8 + nc) * CHUNK_B + off] = f2e4m3(w3[i]);
    if (k < 32) blob[nc * CHUNK_B + off] = f2e4m3(w1[i]);
}

// ------------------------------------------------------------ PTX helpers ---
__device__ __forceinline__ uint32_t scvta(const void* p) {
    return (uint32_t)__cvta_generic_to_shared(p);
}
__device__ __forceinline__ uint32_t lds32(uint32_t addr) {
    uint32_t v;
    asm volatile("ld.shared.b32 %0, [%1];" : "=r"(v) : "r"(addr));
    return v;
}
__device__ __forceinline__ void sts16(uint32_t addr, uint16_t v) {
    asm volatile("st.shared.u16 [%0], %1;" :: "r"(addr), "h"(v));
}
__device__ __forceinline__ void mma_fp8(float* c, const uint32_t* a,
                                        uint32_t b0, uint32_t b1) {
    asm volatile("mma.sync.aligned.m16n8k32.row.col.f32.e4m3.e4m3.f32 "
                 "{%0,%1,%2,%3}, {%4,%5,%6,%7}, {%8,%9}, {%0,%1,%2,%3};"
                 : "+f"(c[0]), "+f"(c[1]), "+f"(c[2]), "+f"(c[3])
                 : "r"(a[0]), "r"(a[1]), "r"(a[2]), "r"(a[3]),
                   "r"(b0), "r"(b1));
}
__device__ __forceinline__ void cp16(uint32_t smem, const void* gmem) {
    asm volatile("cp.async.cg.shared.global [%0], [%1], 16;"
                 :: "r"(smem), "l"(gmem));
}
__device__ __forceinline__ void cp_commit() {
    asm volatile("cp.async.commit_group;");
}
template <int NG>
__device__ __forceinline__ void cp_wait() {
    asm volatile("cp.async.wait_group %0;" :: "n"(NG));
}
// pack two floats as e4m3x2: lo = first arg
__device__ __forceinline__ uint16_t pack_e4m3x2(float lo, float hi) {
    uint16_t u;
    asm("cvt.rn.satfinite.e4m3x2.f32 %0, %1, %2;" : "=h"(u) : "f"(hi), "f"(lo));
    return u;
}

// -------------------------------------------------------------- SMEM map ----
// W ring (2 x 17408) | act A0 (128x272 e4m3) | act A1 | biasS f32[768] | w4 f32[772]
#define WSLOT    17408
#define W_OFF    0
#define A0_OFF   34816
#define A1_OFF   69632
#define BIAS_OFF 104448
#define W4_OFF   107520
#define SMEM_BYTES 110608

// issue cp.async for chunk s into its ring slot (slot = s & 1)
__device__ __forceinline__ void issue_chunk(uint32_t sb, const char* blob,
                                            int s, int tid) {
    uint32_t dst = sb + W_OFF + (uint32_t)(s & 1) * WSLOT;
    const char* src = blob + (size_t)s * CHUNK_B;
    for (uint32_t o = (uint32_t)tid * 16u; o < CHUNK_B; o += THREADS * 16u)
        cp16(dst + o, src + o);
    cp_commit();
}

// MMA over one fp8 W chunk (64 cols), KB kblocks of k=32.
// aBase/wBase already include per-lane offsets: row*272 + 4*(lane&3).
template <int KB>
__device__ __forceinline__ void chunk_fp8(uint32_t aBase, uint32_t wBase,
                                          float (*acc)[4]) {
    #pragma unroll
    for (int kb = 0; kb < KB; kb++) {
        uint32_t ak = aBase + (uint32_t)kb * 32u;
        uint32_t a[4];
        a[0] = lds32(ak);            // row r,   k lo
        a[1] = lds32(ak + 2176u);    // row r+8, k lo   (8*272)
        a[2] = lds32(ak + 16u);      // row r,   k hi
        a[3] = lds32(ak + 2192u);    // row r+8, k hi
        #pragma unroll
        for (int t = 0; t < 8; t++) {
            uint32_t bk = wBase + (uint32_t)t * 2176u + (uint32_t)kb * 32u;
            uint32_t b0 = lds32(bk);
            uint32_t b1 = lds32(bk + 16u);
            mma_fp8(acc[t], a, b0, b1);
        }
    }
}

// bias(scaled) + relu + quantize e4m3 -> store to act buffer.
// acc[t] = n-tile t -> columns colBase + 8*t + 2*c4 (+1)
__device__ __forceinline__ void epi_store_fp8(const float (*acc)[4],
                                              const float* sB, int colBase,
                                              uint32_t outRowBase, int c4) {
    #pragma unroll
    for (int t = 0; t < 8; t++) {
        int col = colBase + 8 * t + 2 * c4;
        float b0v = sB[col], b1v = sB[col + 1];
        uint16_t u0 = pack_e4m3x2(fmaxf(acc[t][0] + b0v, 0.0f),
                                  fmaxf(acc[t][1] + b1v, 0.0f));
        uint16_t u1 = pack_e4m3x2(fmaxf(acc[t][2] + b0v, 0.0f),
                                  fmaxf(acc[t][3] + b1v, 0.0f));
        uint32_t a0 = outRowBase + (uint32_t)col;
        sts16(a0, u0);
        sts16(a0 + 2176u, u1);
    }
}

// --------------------------------- fused encode + fp8 MLP, 2 CTAs per SM ----
__global__ void __launch_bounds__(THREADS, 2)
fused_all(const float* __restrict__ x,
          const float* __restrict__ table,
          const char* __restrict__ blob,
          const float* __restrict__ b1, const float* __restrict__ b2,
          const float* __restrict__ b3, const float* __restrict__ w4,
          const float* __restrict__ b4, float* __restrict__ out, int N) {
    extern __shared__ char smem[];
    const uint32_t sb = scvta(smem);
    float* sBias = (float*)(smem + BIAS_OFF);
    float* sW4   = (float*)(smem + W4_OFF);

    const int tid = threadIdx.x;
    const int lane = tid & 31;
    const int wid = tid >> 5;                // 0..7
    const int m0 = wid * 16;
    const int c4 = lane & 3;
    const int r4 = lane >> 2;
    const int rowBase = blockIdx.x * ROWS;

    // kick off W chunks 0,1 immediately (overlaps encode)
    issue_chunk(sb, blob, 0, tid);
    issue_chunk(sb, blob, 1, tid);

    // ---- scaled biases + final weights ----
    sBias[tid]       = b1[tid] * ACT_SCALE;
    sBias[256 + tid] = b2[tid] * ACT_SCALE;
    sBias[512 + tid] = b3[tid] * ACT_SCALE;
    for (int v = tid; v < 771; v += THREADS)
        sW4[v] = (v < 768) ? w4[v] : b4[v - 768];

    // ---- encode: 2 threads per point, 8 levels each -> fp8 feat in A0 ----
    {
        const int p = tid >> 1;
        const int h = tid & 1;
        const int gp = min(rowBase + p, N - 1);
        float x0 = __ldg(x + 3 * gp + 0) * (1.0f / 1.5f);
        float x1 = __ldg(x + 3 * gp + 1) * (1.0f / 1.5f);
        float x2 = __ldg(x + 3 * gp + 2) * (1.0f / 1.5f);

        #pragma unroll
        for (int li = 0; li < 8; li++) {
            const int l = h * 8 + li;
            float s = c_scale[l];
            float px = x0 * s + 0.5f;
            float py = x1 * s + 0.5f;
            float pz = x2 * s + 0.5f;
            float fx = floorf(px), fy = floorf(py), fz = floorf(pz);
            float tx = px - fx, ty = py - fy, tz = pz - fz;
            uint32_t X = (uint32_t)fx, Y = (uint32_t)fy, Z = (uint32_t)fz;
            float wx[2] = {1.0f - tx, tx};
            float wy[2] = {1.0f - ty, ty};
            float wz[2] = {1.0f - tz, tz};

            float a0 = 0.0f, a1 = 0.0f;
            #pragma unroll
            for (int cc = 0; cc < 8; cc++) {
                uint32_t bx = (uint32_t)(cc & 1);
                uint32_t by = (uint32_t)((cc >> 1) & 1);
                uint32_t bz = (uint32_t)((cc >> 2) & 1);
                uint32_t cx = X + bx, cy = Y + by, cz = Z + bz;
                uint32_t idx;
                if (h == 0 && li < 5) {
                    uint32_t r1 = c_res1[li];
                    idx = cx + cy * r1 + cz * r1 * r1;   // dense
                } else {
                    idx = (cx * 1u ^ cy * 2654435761u ^ cz * 805459861u) & 524287u;
                }
                float w = wx[bx] * wy[by] * wz[bz];
                float2 t2 = __ldg((const float2*)table + (c_offset[l] + (int)idx));
                a0 += w * t2.x;
                a1 += w * t2.y;
            }
            uint16_t u = pack_e4m3x2(a0 * ACT_SCALE, a1 * ACT_SCALE);
            sts16(sb + A0_OFF + (uint32_t)(p * 272 + 2 * l), u);
        }
    }
    // per-lane MMA load bases
    const uint32_t aOff = (uint32_t)((m0 + r4) * 272 + c4 * 4);
    const uint32_t wOff = (uint32_t)(r4 * 272 + c4 * 4);
    const uint32_t outRow0 = (uint32_t)((m0 + r4) * 272);

    float p0[3] = {0.0f, 0.0f, 0.0f};
    float p1[3] = {0.0f, 0.0f, 0.0f};

    // ================= LAYER 1 (K=32 -> 1 kblock, chunks 0..3): A0 -> A1 ====
    #pragma unroll
    for (int c = 0; c < 4; c++) {
        const int s = c;
        cp_wait<1>();
        __syncthreads();   // chunk resident + (c==0) feat stores visible
        uint32_t wBase = sb + W_OFF + (uint32_t)(s & 1) * WSLOT + wOff;
        float acc[8][4];
        #pragma unroll
        for (int j = 0; j < 8; j++)
            #pragma unroll
            for (int q = 0; q < 4; q++) acc[j][q] = 0.0f;
        chunk_fp8<1>(sb + A0_OFF + aOff, wBase, acc);
        epi_store_fp8(acc, sBias, c * 64, sb + A1_OFF + outRow0, c4);
        __syncthreads();   // all warps done reading slot (s&1)
        issue_chunk(sb, blob, s + 2, tid);
    }

    // ================= LAYER 2 (K=256 -> 8 kblocks, chunks 4..7): A1 -> A0 ==
    #pragma unroll
    for (int c = 0; c < 4; c++) {
        const int s = 4 + c;
        cp_wait<1>();
        __syncthreads();   // chunk resident + layer-1 epi stores visible
        uint32_t wBase = sb + W_OFF + (uint32_t)(s & 1) * WSLOT + wOff;
        float acc[8][4];
        #pragma unroll
        for (int j = 0; j < 8; j++)
            #pragma unroll
            for (int q = 0; q < 4; q++) acc[j][q] = 0.0f;
        chunk_fp8<8>(sb + A1_OFF + aOff, wBase, acc);
        epi_store_fp8(acc, sBias + 256, c * 64, sb + A0_OFF + outRow0, c4);
        __syncthreads();
        issue_chunk(sb, blob, s + 2, tid);
    }

    // ================= LAYER 3 (chunks 8..11): A0 -> final regs =============
    #pragma unroll
    for (int c = 0; c < 4; c++) {
        if (c < 3) { cp_wait<1>(); } else { cp_wait<0>(); }
        __syncthreads();
        const int s = 8 + c;
        uint32_t wBase = sb + W_OFF + (uint32_t)(s & 1) * WSLOT + wOff;
        float acc[8][4];
        #pragma unroll
        for (int j = 0; j < 8; j++)
            #pragma unroll
            for (int q = 0; q < 4; q++) acc[j][q] = 0.0f;
        chunk_fp8<8>(sb + A0_OFF + aOff, wBase, acc);
        if (c < 2) {
            __syncthreads();   // done reading slot before refill
            issue_chunk(sb, blob, s + 2, tid);
        }
        // fused final layer: relu then dot with w4 cols (n-tile t -> 8 cols)
        const float* sB3 = sBias + 512;
        #pragma unroll
        for (int t = 0; t < 8; t++) {
            int col0 = c * 64 + t * 8 + 2 * c4;
            float b0v = sB3[col0], b1v = sB3[col0 + 1];
            float v0 = fmaxf(acc[t][0] + b0v, 0.0f);
            float v1 = fmaxf(acc[t][1] + b1v, 0.0f);
            float v2 = fmaxf(acc[t][2] + b0v, 0.0f);
            float v3 = fmaxf(acc[t][3] + b1v, 0.0f);
            #pragma unroll
            for (int j = 0; j < 3; j++) {
                float w0 = sW4[col0 * 3 + j], w1v = sW4[(col0 + 1) * 3 + j];
                p0[j] += v0 * w0 + v1 * w1v;
                p1[j] += v2 * w0 + v3 * w1v;
            }
        }
    }

    // ---- quad reduce (lanes of one row differ in bits 0,1 of lane id) ----
    #pragma unroll
    for (int j = 0; j < 3; j++) {
        p0[j] += __shfl_xor_sync(0xFFFFFFFFu, p0[j], 1);
        p1[j] += __shfl_xor_sync(0xFFFFFFFFu, p1[j], 1);
        p0[j] += __shfl_xor_sync(0xFFFFFFFFu, p0[j], 2);
        p1[j] += __shfl_xor_sync(0xFFFFFFFFu, p1[j], 2);
    }
    if (c4 == 0) {
        int r0 = rowBase + m0 + r4;
        int r1 = r0 + 8;
        if (r0 < N) {
            #pragma unroll
            for (int j = 0; j < 3; j++)
                out[3 * r0 + j] = 1.0f /
                    (1.0f + expf(-(p0[j] * INV_ACT_SCALE + sW4[768 + j])));
        }
        if (r1 < N) {
            #pragma unroll
            for (int j = 0; j < 3; j++)
                out[3 * r1 + j] = 1.0f /
                    (1.0f + expf(-(p1[j] * INV_ACT_SCALE + sW4[768 + j])));
        }
    }
}

// --------------------------------------------------------------- launcher ---
extern "C" void kernel_launch(void* const* d_in, const int* in_sizes, int n_in,
                              void* d_out, int out_size) {
    const float* x     = (const float*)d_in[0];
    const float* table = (const float*)d_in[1];
    const float* w1    = (const float*)d_in[2];
    const float* b1    = (const float*)d_in[3];
    const float* w2    = (const float*)d_in[4];
    const float* b2    = (const float*)d_in[5];
    const float* w3    = (const float*)d_in[6];
    const float* b3    = (const float*)d_in[7];
    const float* w4    = (const float*)d_in[8];
    const float* b4    = (const float*)d_in[9];
    float* out = (float*)d_out;

    int N = in_sizes[0] / 3;

    char* blob;
    cudaGetSymbolAddress((void**)&blob, g_wblob);

    cudaFuncSetAttribute(fused_all, cudaFuncAttributeMaxDynamicSharedMemorySize,
                         SMEM_BYTES);

    cvtw_kernel<<<256, 256>>>(w1, w2, w3, blob);
    fused_all<<<(N + ROWS - 1) / ROWS, THREADS, SMEM_BYTES>>>(
        x, table, blob, b1, b2, b3, w4, b4, out, N);
}

// round 17
// speedup vs baseline: 1.3676x; 1.3676x over previous
#include <cuda_runtime.h>
#include <cuda_bf16.h>
#include <cstdint>

// ---------------- hash-grid constants (precomputed from reference config) ----
__constant__ float c_scale[16] = {
    15.0f,          21.1106061f,   29.5549331f,   41.2242532f,
    57.3502375f,    79.6349472f,  110.4304720f,  152.9872000f,
    211.7969070f,  293.0667790f,  405.3746690f,  560.5743900f,
    775.0469010f, 1071.4291820f, 1481.0036600f, 2047.0f
};
__constant__ uint32_t c_res1[5] = {17u, 24u, 32u, 44u, 60u};
__constant__ int c_offset[16] = {
    0, 4920, 18744, 51512, 136696, 352696, 876984, 1401272,
    1925560, 2449848, 2974136, 3498424, 4022712, 4547000, 5071288, 5595576
};

// W chunk stream: 12 chunks (L1 c0..3, L2 c0..3, L3 c0..3), flat smem images
// (rows = K, 64 cols + 8 pad, stride 72 bf16 = 144 B).
__constant__ uint32_t c_chunk_off[12] = {
    0u, 4608u, 9216u, 13824u,
    18432u, 55296u, 92160u, 129024u,
    165888u, 202752u, 239616u, 276480u
};
__constant__ uint32_t c_chunk_bytes[12] = {
    4608u, 4608u, 4608u, 4608u,
    36864u, 36864u, 36864u, 36864u,
    36864u, 36864u, 36864u, 36864u
};

#define NPTS 524288
#define THREADS 256
#define ROWS 128

// pre-baked weight chunk blob (allocation-free rule: __device__ global)
__device__ char g_wblob[313344];

// ------------------------------------------------------- weight baking ------
__global__ void cvtw_kernel(const float* __restrict__ w1,
                            const float* __restrict__ w2,
                            const float* __restrict__ w3,
                            char* __restrict__ blob) {
    int i = blockIdx.x * 256 + threadIdx.x;   // i = k*256 + n, 65536 total
    int k = i >> 8, n = i & 255;
    uint32_t nc = (uint32_t)(n >> 6);
    uint32_t eoff = ((uint32_t)k * 72u + (uint32_t)(n & 63)) * 2u;
    *(__nv_bfloat16*)(blob + 18432u + nc * 36864u + eoff) = __float2bfloat16(w2[i]);
    *(__nv_bfloat16*)(blob + 165888u + nc * 36864u + eoff) = __float2bfloat16(w3[i]);
    if (k < 32)
        *(__nv_bfloat16*)(blob + nc * 4608u + eoff) = __float2bfloat16(w1[i]);
}

// ------------------------------------------------------------ PTX helpers ---
__device__ __forceinline__ uint32_t scvta(const void* p) {
    return (uint32_t)__cvta_generic_to_shared(p);
}
__device__ __forceinline__ void ldsm_x4(uint32_t* r, uint32_t addr) {
    asm volatile("ldmatrix.sync.aligned.m8n8.x4.shared.b16 {%0,%1,%2,%3}, [%4];"
                 : "=r"(r[0]), "=r"(r[1]), "=r"(r[2]), "=r"(r[3]) : "r"(addr));
}
__device__ __forceinline__ void ldsm_x4_t(uint32_t* r, uint32_t addr) {
    asm volatile("ldmatrix.sync.aligned.m8n8.x4.trans.shared.b16 {%0,%1,%2,%3}, [%4];"
                 : "=r"(r[0]), "=r"(r[1]), "=r"(r[2]), "=r"(r[3]) : "r"(addr));
}
__device__ __forceinline__ void mma_bf16(float* c, const uint32_t* a, const uint32_t* b) {
    asm volatile("mma.sync.aligned.m16n8k16.row.col.f32.bf16.bf16.f32 "
                 "{%0,%1,%2,%3}, {%4,%5,%6,%7}, {%8,%9}, {%0,%1,%2,%3};"
                 : "+f"(c[0]), "+f"(c[1]), "+f"(c[2]), "+f"(c[3])
                 : "r"(a[0]), "r"(a[1]), "r"(a[2]), "r"(a[3]),
                   "r"(b[0]), "r"(b[1]));
}
__device__ __forceinline__ void cp16(uint32_t smem, const void* gmem) {
    asm volatile("cp.async.cg.shared.global [%0], [%1], 16;"
                 :: "r"(smem), "l"(gmem));
}
__device__ __forceinline__ void cp_commit() {
    asm volatile("cp.async.commit_group;");
}
template <int NG>
__device__ __forceinline__ void cp_wait() {
    asm volatile("cp.async.wait_group %0;" :: "n"(NG));
}
__device__ __forceinline__ uint32_t packrelu(float a, float b) {
    __nv_bfloat162 t = __float22bfloat162_rn(
        make_float2(fmaxf(a, 0.0f), fmaxf(b, 0.0f)));
    return *(uint32_t*)&t;
}

// -------------------------------------------------------------- SMEM map ----
// 4-slot W ring (slot = s & 3): chunks processed in pairs; at pair start the
// two slots being refilled held the previous pair (finished by all warps).
#define WSLOT     36864
#define W_OFF     0
#define FEAT_OFF  (4 * WSLOT)                 // 147456 : 128 x 40 bf16
#define SF        40
#define BIAS_OFF  (FEAT_OFF + ROWS * SF * 2)  // 157696 : float[768] b1|b2|b3
#define W4_OFF    (BIAS_OFF + 768 * 4)        // 160768 : float[772] w4|b4
#define SMEM_BYTES (W4_OFF + 772 * 4)         // 163856

// issue cp.async for chunk s into its ring slot (slot = s & 3)
__device__ __forceinline__ void issue_chunk(uint32_t sb, const char* blob,
                                            int s, int tid) {
    uint32_t dst = sb + W_OFF + (uint32_t)(s & 3) * WSLOT;
    uint32_t off = c_chunk_off[s];
    uint32_t bytes = c_chunk_bytes[s];
    for (uint32_t o = (uint32_t)tid * 16u, step = THREADS * 16u; o < bytes; o += step)
        cp16(dst + o, blob + off + o);
    cp_commit();
}

// load kblock kb's B fragments (16 k-rows x 64 cols) from smem chunk
__device__ __forceinline__ void load_bt(uint32_t wBase, int kb, uint32_t (*bt)[4]) {
    uint32_t a = wBase + (uint32_t)kb * 2304u;
    ldsm_x4_t(bt[0], a);
    ldsm_x4_t(bt[1], a + 32u);
    ldsm_x4_t(bt[2], a + 64u);
    ldsm_x4_t(bt[3], a + 96u);
}
__device__ __forceinline__ void mma_bt(float (*acc)[4], const uint32_t* aF,
                                       const uint32_t (*bt)[4]) {
    #pragma unroll
    for (int nq = 0; nq < 4; nq++) {
        mma_bf16(acc[2 * nq],     aF, &bt[nq][0]);
        mma_bf16(acc[2 * nq + 1], aF, &bt[nq][2]);
    }
}

// MMA over a PAIR of W chunks (2 x 64 cols) sharing the same A fragments.
// Two independent accumulator chains per kblock -> 2x MMA ILP.
template <int KB>
__device__ __forceinline__ void chunk_mma2(uint32_t w0, uint32_t w1,
                                           const uint32_t (*aF)[4],
                                           float (*acc0)[4], float (*acc1)[4]) {
    #pragma unroll
    for (int kb = 0; kb < KB; kb++) {
        uint32_t bt0[4][4], bt1[4][4];
        load_bt(w0, kb, bt0);
        load_bt(w1, kb, bt1);
        mma_bt(acc0, aF[kb], bt0);
        mma_bt(acc1, aF[kb], bt1);
    }
}

// bias + relu + C-frag -> next-layer A-frag (bf16) for 4 kblocks (64 cols)
__device__ __forceinline__ void epi_build(const float (*acc)[4],
                                          const float* sB, int colBase,
                                          int l2x, uint32_t (*outA)[4]) {
    #pragma unroll
    for (int t = 0; t < 4; t++) {
        float b00 = sB[colBase + 16 * t + l2x];
        float b01 = sB[colBase + 16 * t + l2x + 1];
        float b10 = sB[colBase + 16 * t + 8 + l2x];
        float b11 = sB[colBase + 16 * t + 8 + l2x + 1];
        const float* cA = acc[2 * t];
        const float* cB = acc[2 * t + 1];
        outA[t][0] = packrelu(cA[0] + b00, cA[1] + b01);
        outA[t][1] = packrelu(cA[2] + b00, cA[3] + b01);
        outA[t][2] = packrelu(cB[0] + b10, cB[1] + b11);
        outA[t][3] = packrelu(cB[2] + b10, cB[3] + b11);
    }
}

// --------------------------------- fused encode + register-resident MLP -----
__global__ void __launch_bounds__(THREADS)
fused_all(const float* __restrict__ x,
          const float* __restrict__ table,
          const char* __restrict__ blob,
          const float* __restrict__ b1, const float* __restrict__ b2,
          const float* __restrict__ b3, const float* __restrict__ w4,
          const float* __restrict__ b4, float* __restrict__ out, int N) {
    extern __shared__ char smem[];
    const uint32_t sb = scvta(smem);
    __nv_bfloat16* sFeat = (__nv_bfloat16*)(smem + FEAT_OFF);
    float* sBias = (float*)(smem + BIAS_OFF);
    float* sW4   = (float*)(smem + W4_OFF);

    const int tid = threadIdx.x;
    const int lane = tid & 31;
    const int wid = tid >> 5;                // 0..7
    const int m0 = wid * 16;
    const int lr2 = lane & 15;
    const int lc2 = (lane >> 4) << 3;
    const int l2x = (lane & 3) * 2;
    const int rowBase = blockIdx.x * ROWS;
    const uint32_t wWarpOff = (uint32_t)((lr2 * 72 + lc2) * 2);

    // prefetch W chunks 0..3 immediately (overlaps encode; fills all 4 slots)
    issue_chunk(sb, blob, 0, tid);
    issue_chunk(sb, blob, 1, tid);
    issue_chunk(sb, blob, 2, tid);
    issue_chunk(sb, blob, 3, tid);

    // ---- biases + final weights ----
    sBias[tid]       = b1[tid];
    sBias[256 + tid] = b2[tid];
    sBias[512 + tid] = b3[tid];
    for (int v = tid; v < 771; v += THREADS)
        sW4[v] = (v < 768) ? w4[v] : b4[v - 768];

    // ---- encode: 2 threads per point, 8 levels each -> feat smem ----
    {
        const int p = tid >> 1;
        const int h = tid & 1;
        const int gp = min(rowBase + p, N - 1);
        float x0 = __ldg(x + 3 * gp + 0) * (1.0f / 1.5f);
        float x1 = __ldg(x + 3 * gp + 1) * (1.0f / 1.5f);
        float x2 = __ldg(x + 3 * gp + 2) * (1.0f / 1.5f);

        #pragma unroll
        for (int li = 0; li < 8; li++) {
            const int l = h * 8 + li;
            float s = c_scale[l];
            float px = x0 * s + 0.5f;
            float py = x1 * s + 0.5f;
            float pz = x2 * s + 0.5f;
            float fx = floorf(px), fy = floorf(py), fz = floorf(pz);
            float tx = px - fx, ty = py - fy, tz = pz - fz;
            uint32_t X = (uint32_t)fx, Y = (uint32_t)fy, Z = (uint32_t)fz;
            float wx[2] = {1.0f - tx, tx};
            float wy[2] = {1.0f - ty, ty};
            float wz[2] = {1.0f - tz, tz};

            float a0 = 0.0f, a1 = 0.0f;
            #pragma unroll
            for (int cc = 0; cc < 8; cc++) {
                uint32_t bx = (uint32_t)(cc & 1);
                uint32_t by = (uint32_t)((cc >> 1) & 1);
                uint32_t bz = (uint32_t)((cc >> 2) & 1);
                uint32_t cx = X + bx, cy = Y + by, cz = Z + bz;
                uint32_t idx;
                if (h == 0 && li < 5) {
                    uint32_t r1 = c_res1[li];
                    idx = cx + cy * r1 + cz * r1 * r1;   // dense
                } else {
                    idx = (cx * 1u ^ cy * 2654435761u ^ cz * 805459861u) & 524287u;
                }
                float w = wx[bx] * wy[by] * wz[bz];
                float2 t2 = __ldg((const float2*)table + (c_offset[l] + (int)idx));
                a0 += w * t2.x;
                a1 += w * t2.y;
            }
            *(__nv_bfloat162*)(sFeat + p * SF + 2 * l) =
                __float22bfloat162_rn(make_float2(a0, a1));
        }
    }
    __syncthreads();   // feat visible to all warps

    // A fragments for layer 1 (K=32 -> 2 kblocks); rows m0..m0+15
    uint32_t a1f[2][4];
    #pragma unroll
    for (int kb = 0; kb < 2; kb++)
        ldsm_x4(a1f[kb], sb + FEAT_OFF
                + (uint32_t)(((m0 + lr2) * SF + kb * 16 + lc2) * 2));

    uint32_t a2f[16][4];
    uint32_t a3f[16][4];
    float p0[3] = {0.0f, 0.0f, 0.0f};
    float p1[3] = {0.0f, 0.0f, 0.0f};

    // ================= LAYER 1 (K=32, pairs q=0,1 -> chunks 2q,2q+1) ========
    #pragma unroll
    for (int q = 0; q < 2; q++) {
        cp_wait<2>();      // chunks 2q,2q+1 resident (2 groups in flight)
        __syncthreads();
        uint32_t w0 = sb + W_OFF + (uint32_t)((2 * q)     & 3) * WSLOT + wWarpOff;
        uint32_t w1 = sb + W_OFF + (uint32_t)((2 * q + 1) & 3) * WSLOT + wWarpOff;
        float acc0[8][4], acc1[8][4];
        #pragma unroll
        for (int j = 0; j < 8; j++)
            #pragma unroll
            for (int qq = 0; qq < 4; qq++) { acc0[j][qq] = 0.0f; acc1[j][qq] = 0.0f; }
        chunk_mma2<2>(w0, w1, a1f, acc0, acc1);
        epi_build(acc0, sBias, q * 128,      l2x, &a2f[8 * q]);
        epi_build(acc1, sBias, q * 128 + 64, l2x, &a2f[8 * q + 4]);
        __syncthreads();   // all warps done reading both slots
        issue_chunk(sb, blob, 2 * q + 4, tid);
        issue_chunk(sb, blob, 2 * q + 5, tid);
    }

    // ================= LAYER 2 (K=256, pairs q=0,1 -> chunks 4+2q,5+2q) =====
    #pragma unroll
    for (int q = 0; q < 2; q++) {
        const int s = 4 + 2 * q;
        cp_wait<2>();
        __syncthreads();
        uint32_t w0 = sb + W_OFF + (uint32_t)(s & 3) * WSLOT + wWarpOff;
        uint32_t w1 = sb + W_OFF + (uint32_t)((s + 1) & 3) * WSLOT + wWarpOff;
        float acc0[8][4], acc1[8][4];
        #pragma unroll
        for (int j = 0; j < 8; j++)
            #pragma unroll
            for (int qq = 0; qq < 4; qq++) { acc0[j][qq] = 0.0f; acc1[j][qq] = 0.0f; }
        chunk_mma2<16>(w0, w1, a2f, acc0, acc1);
        epi_build(acc0, sBias + 256, q * 128,      l2x, &a3f[8 * q]);
        epi_build(acc1, sBias + 256, q * 128 + 64, l2x, &a3f[8 * q + 4]);
        __syncthreads();
        issue_chunk(sb, blob, s + 4, tid);
        issue_chunk(sb, blob, s + 5, tid);
    }

    // ================= LAYER 3 (K=256, pairs q=0,1 -> chunks 8+2q) + final ==
    #pragma unroll
    for (int q = 0; q < 2; q++) {
        const int s = 8 + 2 * q;
        if (q == 0) { cp_wait<2>(); } else { cp_wait<0>(); }
        __syncthreads();
        uint32_t w0 = sb + W_OFF + (uint32_t)(s & 3) * WSLOT + wWarpOff;
        uint32_t w1 = sb + W_OFF + (uint32_t)((s + 1) & 3) * WSLOT + wWarpOff;
        float acc0[8][4], acc1[8][4];
        #pragma unroll
        for (int j = 0; j < 8; j++)
            #pragma unroll
            for (int qq = 0; qq < 4; qq++) { acc0[j][qq] = 0.0f; acc1[j][qq] = 0.0f; }
        chunk_mma2<16>(w0, w1, a3f, acc0, acc1);
        // fused final layer on both chunks (cols q*128 .. q*128+127)
        const float* sB3 = sBias + 512;
        #pragma unroll
        for (int half = 0; half < 2; half++) {
            const float (*acc)[4] = half ? acc1 : acc0;
            const int colBase = q * 128 + half * 64;
            #pragma unroll
            for (int t = 0; t < 8; t++) {
                int col0 = colBase + t * 8 + l2x;
                float b0v = sB3[col0], b1v = sB3[col0 + 1];
                float v0 = fmaxf(acc[t][0] + b0v, 0.0f);
                float v1 = fmaxf(acc[t][1] + b1v, 0.0f);
                float v2 = fmaxf(acc[t][2] + b0v, 0.0f);
                float v3 = fmaxf(acc[t][3] + b1v, 0.0f);
                #pragma unroll
                for (int j = 0; j < 3; j++) {
                    float w0v = sW4[col0 * 3 + j], w1v = sW4[(col0 + 1) * 3 + j];
                    p0[j] += v0 * w0v + v1 * w1v;
                    p1[j] += v2 * w0v + v3 * w1v;
                }
            }
        }
    }

    // ---- quad reduce (lanes of one row differ in bits 0,1 of lane id) ----
    #pragma unroll
    for (int j = 0; j < 3; j++) {
        p0[j] += __shfl_xor_sync(0xFFFFFFFFu, p0[j], 1);
        p1[j] += __shfl_xor_sync(0xFFFFFFFFu, p1[j], 1);
        p0[j] += __shfl_xor_sync(0xFFFFFFFFu, p0[j], 2);
        p1[j] += __shfl_xor_sync(0xFFFFFFFFu, p1[j], 2);
    }
    if ((lane & 3) == 0) {
        int r0 = rowBase + m0 + (lane >> 2);
        int r1 = r0 + 8;
        if (r0 < N) {
            #pragma unroll
            for (int j = 0; j < 3; j++)
                out[3 * r0 + j] = 1.0f / (1.0f + expf(-(p0[j] + sW4[768 + j])));
        }
        if (r1 < N) {
            #pragma unroll
            for (int j = 0; j < 3; j++)
                out[3 * r1 + j] = 1.0f / (1.0f + expf(-(p1[j] + sW4[768 + j])));
        }
    }
}

// --------------------------------------------------------------- launcher ---
extern "C" void kernel_launch(void* const* d_in, const int* in_sizes, int n_in,
                              void* d_out, int out_size) {
    const float* x     = (const float*)d_in[0];
    const float* table = (const float*)d_in[1];
    const float* w1    = (const float*)d_in[2];
    const float* b1    = (const float*)d_in[3];
    const float* w2    = (const float*)d_in[4];
    const float* b2    = (const float*)d_in[5];
    const float* w3    = (const float*)d_in[6];
    const float* b3    = (const float*)d_in[7];
    const float* w4    = (const float*)d_in[8];
    const float* b4    = (const float*)d_in[9];
    float* out = (float*)d_out;

    int N = in_sizes[0] / 3;

    char* blob;
    cudaGetSymbolAddress((void**)&blob, g_wblob);

    cudaFuncSetAttribute(fused_all, cudaFuncAttributeMaxDynamicSharedMemorySize,
                         SMEM_BYTES);

    cvtw_kernel<<<256, 256>>>(w1, w2, w3, blob);
    fused_all<<<(N + ROWS - 1) / ROWS, THREADS, SMEM_BYTES>>>(
        x, table, blob, b1, b2, b3, w4, b4, out, N);
}